// round 1
// baseline (speedup 1.0000x reference)
#include <cuda_runtime.h>
#include <cuda_bf16.h>

#define EPS 1e-5f

typedef unsigned long long u64;

// ---------------- f32x2 packed helpers (sm_103a) ----------------
__device__ __forceinline__ u64 pk2(float lo, float hi) {
    u64 r;
    asm("mov.b64 %0, {%1, %2};" : "=l"(r) : "f"(lo), "f"(hi));
    return r;
}
__device__ __forceinline__ void upk2(u64 v, float& lo, float& hi) {
    asm("mov.b64 {%0, %1}, %2;" : "=f"(lo), "=f"(hi) : "l"(v));
}
__device__ __forceinline__ u64 ffma2_(u64 a, u64 b, u64 c) {
    u64 d;
    asm("fma.rn.f32x2 %0, %1, %2, %3;" : "=l"(d) : "l"(a), "l"(b), "l"(c));
    return d;
}
__device__ __forceinline__ u64 fmul2_(u64 a, u64 b) {
    u64 d;
    asm("mul.rn.f32x2 %0, %1, %2;" : "=l"(d) : "l"(a), "l"(b));
    return d;
}

// ---------------- scratch (no allocations allowed) ----------------
__device__ float  g_x_nhwc[4 * 64 * 64 * 256];   // 16 MB, [b][h][w][c]
__device__ int2   g_p_idx[4 * 9 * 64 * 64];      // per-tap (y0, x0)
__device__ float4 g_cw[4 * 9 * 64 * 64];         // per-tap corner weights
__device__ float2 g_pw2[256 * 128];              // [c][oid] = (pw[oid][c]*s, pw[oid+128][c]*s)
__device__ float  g_bias[256];

// ---------------- kernel 1: NCHW -> NHWC transpose ----------------
__global__ void k_transpose(const float* __restrict__ x) {
    __shared__ float tile[32][33];
    int b  = blockIdx.z;
    int s0 = blockIdx.x * 32;   // hw
    int c0 = blockIdx.y * 32;   // c
    int tx = threadIdx.x, ty = threadIdx.y;  // (32, 8)
    const float* xb = x + (size_t)b * 256 * 4096;
    float* ob = g_x_nhwc + (size_t)b * 4096 * 256;
#pragma unroll
    for (int i = 0; i < 32; i += 8)
        tile[ty + i][tx] = xb[(c0 + ty + i) * 4096 + s0 + tx];
    __syncthreads();
#pragma unroll
    for (int i = 0; i < 32; i += 8)
        ob[(s0 + ty + i) * 256 + c0 + tx] = tile[tx][ty + i];
}

// ---------------- kernel 2: weight prep (fold BN into pw) ----------------
__global__ void k_prep(const float* __restrict__ pw, const float* __restrict__ bg,
                       const float* __restrict__ bb, const float* __restrict__ bm,
                       const float* __restrict__ bv) {
    int idx = blockIdx.x * 256 + threadIdx.x;   // 32768 total
    int oid = idx & 127;
    int cc  = idx >> 7;
    float s0 = bg[oid] * rsqrtf(bv[oid] + EPS);
    float s1 = bg[oid + 128] * rsqrtf(bv[oid + 128] + EPS);
    g_pw2[cc * 128 + oid] = make_float2(pw[oid * 256 + cc] * s0,
                                        pw[(oid + 128) * 256 + cc] * s1);
    if (idx < 256) {
        float s = bg[idx] * rsqrtf(bv[idx] + EPS);
        g_bias[idx] = bb[idx] - bm[idx] * s;
    }
}

// ---------------- kernel 3: offset conv + BN + ReLU + sampling params ----------------
// block = 64 threads (one (b,h) row), grid = 256
__global__ void k_offset(const float* __restrict__ gf, const float* __restrict__ offw,
                         const float* __restrict__ og, const float* __restrict__ obt,
                         const float* __restrict__ om, const float* __restrict__ ov) {
    __shared__ __align__(16) float2 s_w2[9][64][10];  // [k][g][tap(9, pad 10)] = (w_dy, w_dx)
    int bh = blockIdx.x;
    int b = bh >> 6, h = bh & 63;
    int w = threadIdx.x;   // 0..63

    // stage packed weights: dy = channel 2k, dx = channel 2k+1
    for (int i = w; i < 9 * 64 * 9; i += 64) {
        int t = i % 9;
        int g = (i / 9) & 63;
        int k = i / 576;
        float wdy = offw[(2 * k) * 576 + g * 9 + t];
        float wdx = offw[(2 * k + 1) * 576 + g * 9 + t];
        s_w2[k][g][t] = make_float2(wdy, wdx);
    }
    __syncthreads();

    u64 acc[9];
#pragma unroll
    for (int k = 0; k < 9; k++) acc[k] = 0ull;

    const float* gfb = gf + (size_t)b * 64 * 64 * 64;
    for (int g = 0; g < 64; g++) {
        float a[9];
#pragma unroll
        for (int r = 0; r < 3; r++) {
            int hh = h + r - 1;
            bool hv = (unsigned)hh < 64u;
#pragma unroll
            for (int q = 0; q < 3; q++) {
                int ww = w + q - 1;
                bool wv2 = (unsigned)ww < 64u;
                a[r * 3 + q] = (hv && wv2) ? __ldg(gfb + (g * 64 + hh) * 64 + ww) : 0.f;
            }
        }
        u64 a2[9];
#pragma unroll
        for (int t = 0; t < 9; t++) a2[t] = pk2(a[t], a[t]);
#pragma unroll
        for (int k = 0; k < 9; k++) {
            const u64* wr = (const u64*)&s_w2[k][g][0];
            ulonglong2 w01 = *(const ulonglong2*)(wr + 0);
            ulonglong2 w23 = *(const ulonglong2*)(wr + 2);
            ulonglong2 w45 = *(const ulonglong2*)(wr + 4);
            ulonglong2 w67 = *(const ulonglong2*)(wr + 6);
            u64 w8 = wr[8];
            acc[k] = ffma2_(w01.x, a2[0], acc[k]);
            acc[k] = ffma2_(w01.y, a2[1], acc[k]);
            acc[k] = ffma2_(w23.x, a2[2], acc[k]);
            acc[k] = ffma2_(w23.y, a2[3], acc[k]);
            acc[k] = ffma2_(w45.x, a2[4], acc[k]);
            acc[k] = ffma2_(w45.y, a2[5], acc[k]);
            acc[k] = ffma2_(w67.x, a2[6], acc[k]);
            acc[k] = ffma2_(w67.y, a2[7], acc[k]);
            acc[k] = ffma2_(w8,    a2[8], acc[k]);
        }
    }

#pragma unroll
    for (int k = 0; k < 9; k++) {
        float dyr, dxr;
        upk2(acc[k], dyr, dxr);
        int j0 = 2 * k, j1 = 2 * k + 1;
        float s0 = og[j0] * rsqrtf(ov[j0] + EPS);
        float s1 = og[j1] * rsqrtf(ov[j1] + EPS);
        float dy = fmaxf((dyr - om[j0]) * s0 + obt[j0], 0.f);
        float dx = fmaxf((dxr - om[j1]) * s1 + obt[j1], 0.f);
        float ky = (float)((k / 3) - 1) * 2.0f;   // DIL = 2
        float kx = (float)((k % 3) - 1) * 2.0f;
        float gy = (float)h + ky + dy;
        float gx = (float)w + kx + dx;
        float y0f = floorf(gy), x0f = floorf(gx);
        float wy = gy - y0f, wx = gx - x0f;
        float omwy = 1.f - wy, omwx = 1.f - wx;
        int idx = ((b * 9 + k) * 64 + h) * 64 + w;
        g_p_idx[idx] = make_int2((int)y0f, (int)x0f);
        g_cw[idx] = make_float4(omwy * omwx, omwy * wx, wy * omwx, wy * wx);
    }
}

// ---------------- kernel 4: fused sample + depthwise + pointwise + BN/ReLU ----------------
// block = 256 threads, handles 16 consecutive w of one (b,h). grid = 1024
__global__ __launch_bounds__(256) void k_main(const float* __restrict__ dw,
                                              float* __restrict__ out) {
    __shared__ __align__(16) float s_mid[256][20];     // [c][pixel, pad 20]
    __shared__ int2 s_idx[9][16];
    __shared__ __align__(16) u64 s_cw[9][16][4];       // packed corner weights
    __shared__ float s_o[256 * 17];

    int t  = blockIdx.x;
    int w0 = (t & 3) << 4;
    int h  = (t >> 2) & 63;
    int b  = t >> 8;
    int tid = threadIdx.x;

    if (tid < 144) {
        int k = tid / 16, p = tid & 15;
        int idx = ((b * 9 + k) * 64 + h) * 64 + w0 + p;
        s_idx[k][p] = g_p_idx[idx];
        float4 cw = g_cw[idx];
        s_cw[k][p][0] = pk2(cw.x, cw.x);
        s_cw[k][p][1] = pk2(cw.y, cw.y);
        s_cw[k][p][2] = pk2(cw.z, cw.z);
        s_cw[k][p][3] = pk2(cw.w, cw.w);
    }

    // phase 1: each thread owns channel pair (c, c+1) and 8 pixels
    int cp = tid & 127;
    int c  = cp * 2;
    int ph = tid >> 7;
    u64 dw2[9];
#pragma unroll
    for (int k = 0; k < 9; k++)
        dw2[k] = pk2(__ldg(dw + c * 9 + k), __ldg(dw + (c + 1) * 9 + k));
    __syncthreads();

    const float* xb = g_x_nhwc + (size_t)b * 4096 * 256;
#pragma unroll 2
    for (int pp = 0; pp < 8; pp++) {
        int p = (ph << 3) + pp;
        u64 acc = 0ull;
#pragma unroll
        for (int k = 0; k < 9; k++) {
            int2 i2 = s_idx[k][p];
            int y0 = i2.x, x0 = i2.y;
            bool yv0 = (unsigned)y0 < 64u;
            bool yv1 = (unsigned)(y0 + 1) < 64u;
            bool xv0 = (unsigned)x0 < 64u;
            bool xv1 = (unsigned)(x0 + 1) < 64u;
            const float* bp = xb + (y0 * 64 + x0) * 256 + c;
            u64 v00 = (yv0 && xv0) ? __ldg((const u64*)bp) : 0ull;
            u64 v01 = (yv0 && xv1) ? __ldg((const u64*)(bp + 256)) : 0ull;
            u64 v10 = (yv1 && xv0) ? __ldg((const u64*)(bp + 16384)) : 0ull;
            u64 v11 = (yv1 && xv1) ? __ldg((const u64*)(bp + 16640)) : 0ull;
            ulonglong2 cw01 = *(const ulonglong2*)&s_cw[k][p][0];
            ulonglong2 cw23 = *(const ulonglong2*)&s_cw[k][p][2];
            u64 bil = fmul2_(cw01.x, v00);
            bil = ffma2_(cw01.y, v01, bil);
            bil = ffma2_(cw23.x, v10, bil);
            bil = ffma2_(cw23.y, v11, bil);
            acc = ffma2_(dw2[k], bil, acc);
        }
        float a0, a1;
        upk2(acc, a0, a1);
        s_mid[c][p]     = a0;
        s_mid[c + 1][p] = a1;
    }
    __syncthreads();

    // phase 2: each thread owns outputs (oid, oid+128) x 8 pixels
    int oid = tid & 127;
    int pg  = tid >> 7;
    u64 acc2[4], acc3[4];
#pragma unroll
    for (int i = 0; i < 4; i++) { acc2[i] = 0ull; acc3[i] = 0ull; }

    const float2* pwp = g_pw2 + oid;
#pragma unroll 4
    for (int cc = 0; cc < 256; cc++) {
        float2 wv = __ldg(pwp + cc * 128);
        u64 w0p = pk2(wv.x, wv.x);
        u64 w1p = pk2(wv.y, wv.y);
        const ulonglong2* mr = (const ulonglong2*)&s_mid[cc][pg * 8];
        ulonglong2 m01 = mr[0];
        ulonglong2 m23 = mr[1];
        acc2[0] = ffma2_(w0p, m01.x, acc2[0]);
        acc2[1] = ffma2_(w0p, m01.y, acc2[1]);
        acc2[2] = ffma2_(w0p, m23.x, acc2[2]);
        acc2[3] = ffma2_(w0p, m23.y, acc2[3]);
        acc3[0] = ffma2_(w1p, m01.x, acc3[0]);
        acc3[1] = ffma2_(w1p, m01.y, acc3[1]);
        acc3[2] = ffma2_(w1p, m23.x, acc3[2]);
        acc3[3] = ffma2_(w1p, m23.y, acc3[3]);
    }

    float bias0 = g_bias[oid];
    float bias1 = g_bias[oid + 128];
#pragma unroll
    for (int i = 0; i < 4; i++) {
        float lo, hi;
        int p = pg * 8 + i * 2;
        upk2(acc2[i], lo, hi);
        s_o[oid * 17 + p]     = fmaxf(lo + bias0, 0.f);
        s_o[oid * 17 + p + 1] = fmaxf(hi + bias0, 0.f);
        upk2(acc3[i], lo, hi);
        s_o[(oid + 128) * 17 + p]     = fmaxf(lo + bias1, 0.f);
        s_o[(oid + 128) * 17 + p + 1] = fmaxf(hi + bias1, 0.f);
    }
    __syncthreads();

    float* ob = out + (size_t)b * 256 * 4096 + h * 64 + w0;
    for (int i = tid; i < 4096; i += 256) {
        ob[(i >> 4) * 4096 + (i & 15)] = s_o[(i >> 4) * 17 + (i & 15)];
    }
}

// ---------------- launch ----------------
extern "C" void kernel_launch(void* const* d_in, const int* in_sizes, int n_in,
                              void* d_out, int out_size) {
    const float* x    = (const float*)d_in[0];
    const float* gf   = (const float*)d_in[1];
    const float* offw = (const float*)d_in[2];
    const float* og   = (const float*)d_in[3];
    const float* obt  = (const float*)d_in[4];
    const float* om   = (const float*)d_in[5];
    const float* ov   = (const float*)d_in[6];
    const float* dww  = (const float*)d_in[7];
    const float* pww  = (const float*)d_in[8];
    const float* bg   = (const float*)d_in[9];
    const float* bb   = (const float*)d_in[10];
    const float* bm   = (const float*)d_in[11];
    const float* bv   = (const float*)d_in[12];
    float* out = (float*)d_out;

    k_transpose<<<dim3(128, 8, 4), dim3(32, 8)>>>(x);
    k_prep<<<128, 256>>>(pww, bg, bb, bm, bv);
    k_offset<<<256, 64>>>(gf, offw, og, obt, om, ov);
    k_main<<<1024, 256>>>(dww, out);
}